// round 2
// baseline (speedup 1.0000x reference)
#include <cuda_runtime.h>
#include <cuda_bf16.h>
#include <cstdint>

#define T_TOK   8192
#define H_DIM   2048
#define I_DIM   4096
#define NE      8
#define TOPK    2
#define CAP     8192      // per-expert row capacity for Hm scratch (expected ~2048)
#define LISTCAP 16384     // per-expert token list capacity (hard upper bound T*K)

// ---- scratch (static device globals; no allocations allowed) ----
__device__ int   g_cnt[NE];
__device__ int   g_tok[NE * LISTCAP];
__device__ float g_coef[NE * LISTCAP];
__device__ float g_hm[(size_t)NE * CAP * I_DIM];   // 1 GB intermediate h = silu(g)*u

// --------------------------------------------------------------------------
__global__ void k_clear(float* __restrict__ out, size_t n) {
    size_t i = (size_t)blockIdx.x * blockDim.x + threadIdx.x;
    if (i < n) out[i] = 0.0f;
    if (blockIdx.x == 0 && threadIdx.x < NE) g_cnt[threadIdx.x] = 0;
}

__global__ void k_route(const int* __restrict__ rt, const float* __restrict__ rw) {
    int t = blockIdx.x * blockDim.x + threadIdx.x;
    if (t >= T_TOK) return;
#pragma unroll
    for (int k = 0; k < TOPK; ++k) {
        int   e = rt[t * TOPK + k];
        float w = rw[t * TOPK + k];
        int pos = atomicAdd(&g_cnt[e], 1);
        g_tok[e * LISTCAP + pos]  = t;
        g_coef[e * LISTCAP + pos] = w;
    }
}

// --------------------------------------------------------------------------
// bf16 hi/lo split of a float4, packed for 8-byte smem stores
__device__ __forceinline__ void split4(float4 v, uint2& hu, uint2& lu) {
    float f0 = v.x, f1 = v.y, f2 = v.z, f3 = v.w;
    __nv_bfloat16 h0 = __float2bfloat16(f0);
    __nv_bfloat16 h1 = __float2bfloat16(f1);
    __nv_bfloat16 h2 = __float2bfloat16(f2);
    __nv_bfloat16 h3 = __float2bfloat16(f3);
    __nv_bfloat16 l0 = __float2bfloat16(f0 - __bfloat162float(h0));
    __nv_bfloat16 l1 = __float2bfloat16(f1 - __bfloat162float(h1));
    __nv_bfloat16 l2 = __float2bfloat16(f2 - __bfloat162float(h2));
    __nv_bfloat16 l3 = __float2bfloat16(f3 - __bfloat162float(h3));
    __nv_bfloat162 a; a.x = h0; a.y = h1;
    __nv_bfloat162 b; b.x = h2; b.y = h3;
    __nv_bfloat162 c; c.x = l0; c.y = l1;
    __nv_bfloat162 d; d.x = l2; d.y = l3;
    hu.x = *reinterpret_cast<unsigned*>(&a);
    hu.y = *reinterpret_cast<unsigned*>(&b);
    lu.x = *reinterpret_cast<unsigned*>(&c);
    lu.y = *reinterpret_cast<unsigned*>(&d);
}

__device__ __forceinline__ void mma_bf16(float* c, const uint32_t* a, const uint32_t* b) {
    asm volatile(
        "mma.sync.aligned.m16n8k16.row.col.f32.bf16.bf16.f32 "
        "{%0,%1,%2,%3}, {%4,%5,%6,%7}, {%8,%9}, {%0,%1,%2,%3};\n"
        : "+f"(c[0]), "+f"(c[1]), "+f"(c[2]), "+f"(c[3])
        : "r"(a[0]), "r"(a[1]), "r"(a[2]), "r"(a[3]), "r"(b[0]), "r"(b[1]));
}

#define SMSTRIDE 40

// --------------------------------------------------------------------------
// GEMM1: for expert e, rows = gathered tokens, cols interleave gate/up so that
// each mma c-pair (c0,c1) = (gate_j, up_j). Epilogue applies SwiGLU -> g_hm.
__global__ __launch_bounds__(256, 1) void k_gemm1(const float* __restrict__ x,
                                                  const float* __restrict__ w13) {
    __shared__ __nv_bfloat16 sAh[128][SMSTRIDE], sAl[128][SMSTRIDE];
    __shared__ __nv_bfloat16 sBh[128][SMSTRIDE], sBl[128][SMSTRIDE];

    const int e      = blockIdx.y;
    const int cnt    = g_cnt[e];
    const int tile_m = blockIdx.x >> 6;   // 0..63
    const int tile_n = blockIdx.x & 63;   // 0..63
    const int m0     = tile_m * 128;
    if (m0 >= cnt) return;
    const int n0     = tile_n * 64;       // gate/up column base (in I space)

    const int tid  = threadIdx.x;
    const int lrow = tid >> 3;
    const int lcol = (tid & 7) << 2;

    const int* tokp = g_tok + e * LISTCAP;
    const float* w13e = w13 + (size_t)e * (2 * I_DIM) * H_DIM;

    const float* aPtr[4];
    const float* bPtr[4];
#pragma unroll
    for (int p = 0; p < 4; ++p) {
        int m   = m0 + lrow + 32 * p;
        int tok = (m < cnt) ? tokp[m] : 0;
        aPtr[p] = x + (size_t)tok * H_DIM + lcol;
        int n   = lrow + 32 * p;
        int src = (n & 1) ? (I_DIM + n0 + (n >> 1)) : (n0 + (n >> 1));
        bPtr[p] = w13e + (size_t)src * H_DIM + lcol;
    }

    const int lane = tid & 31, wid = tid >> 5;
    const int warp_m = wid >> 2, warp_n = wid & 3;
    const int gq = lane >> 2, t4 = lane & 3;

    float acc[4][4][4];
#pragma unroll
    for (int a = 0; a < 4; ++a)
#pragma unroll
        for (int b = 0; b < 4; ++b)
#pragma unroll
            for (int c = 0; c < 4; ++c) acc[a][b][c] = 0.0f;

    float4 av[4], bv[4];
#pragma unroll
    for (int p = 0; p < 4; ++p) { av[p] = *(const float4*)(aPtr[p]); bv[p] = *(const float4*)(bPtr[p]); }

    const int KT = H_DIM / 32;
#pragma unroll 1
    for (int kt = 0; kt < KT; ++kt) {
#pragma unroll
        for (int p = 0; p < 4; ++p) {
            uint2 hu, lu;
            split4(av[p], hu, lu);
            *reinterpret_cast<uint2*>(&sAh[lrow + 32 * p][lcol]) = hu;
            *reinterpret_cast<uint2*>(&sAl[lrow + 32 * p][lcol]) = lu;
            split4(bv[p], hu, lu);
            *reinterpret_cast<uint2*>(&sBh[lrow + 32 * p][lcol]) = hu;
            *reinterpret_cast<uint2*>(&sBl[lrow + 32 * p][lcol]) = lu;
        }
        __syncthreads();
        if (kt + 1 < KT) {
            int k0 = (kt + 1) * 32;
#pragma unroll
            for (int p = 0; p < 4; ++p) { av[p] = *(const float4*)(aPtr[p] + k0); bv[p] = *(const float4*)(bPtr[p] + k0); }
        }
#pragma unroll
        for (int kk = 0; kk < 32; kk += 16) {
            uint32_t bh[4][2], bl[4][2];
#pragma unroll
            for (int nf = 0; nf < 4; ++nf) {
                const __nv_bfloat16* ph = &sBh[warp_n * 32 + nf * 8 + gq][kk + t4 * 2];
                bh[nf][0] = *reinterpret_cast<const uint32_t*>(ph);
                bh[nf][1] = *reinterpret_cast<const uint32_t*>(ph + 8);
                const __nv_bfloat16* pl = &sBl[warp_n * 32 + nf * 8 + gq][kk + t4 * 2];
                bl[nf][0] = *reinterpret_cast<const uint32_t*>(pl);
                bl[nf][1] = *reinterpret_cast<const uint32_t*>(pl + 8);
            }
#pragma unroll
            for (int mf = 0; mf < 4; ++mf) {
                uint32_t ah[4], al[4];
                const __nv_bfloat16* ph = &sAh[warp_m * 64 + mf * 16 + gq][kk + t4 * 2];
                ah[0] = *reinterpret_cast<const uint32_t*>(ph);
                ah[1] = *reinterpret_cast<const uint32_t*>(ph + 8 * SMSTRIDE);
                ah[2] = *reinterpret_cast<const uint32_t*>(ph + 8);
                ah[3] = *reinterpret_cast<const uint32_t*>(ph + 8 * SMSTRIDE + 8);
                const __nv_bfloat16* pl = &sAl[warp_m * 64 + mf * 16 + gq][kk + t4 * 2];
                al[0] = *reinterpret_cast<const uint32_t*>(pl);
                al[1] = *reinterpret_cast<const uint32_t*>(pl + 8 * SMSTRIDE);
                al[2] = *reinterpret_cast<const uint32_t*>(pl + 8);
                al[3] = *reinterpret_cast<const uint32_t*>(pl + 8 * SMSTRIDE + 8);
#pragma unroll
                for (int nf = 0; nf < 4; ++nf) {
                    mma_bf16(acc[mf][nf], ah, bh[nf]);
                    mma_bf16(acc[mf][nf], ah, bl[nf]);
                    mma_bf16(acc[mf][nf], al, bh[nf]);
                }
            }
        }
        __syncthreads();
    }

    float* hme = g_hm + (size_t)e * CAP * I_DIM;
#pragma unroll
    for (int mf = 0; mf < 4; ++mf) {
        int row = m0 + warp_m * 64 + mf * 16 + gq;
#pragma unroll
        for (int nf = 0; nf < 4; ++nf) {
            int j = n0 + warp_n * 16 + nf * 4 + t4;
            float g0 = acc[mf][nf][0], u0 = acc[mf][nf][1];
            float g1 = acc[mf][nf][2], u1 = acc[mf][nf][3];
            hme[(size_t)row * I_DIM + j]       = (g0 / (1.0f + expf(-g0))) * u0;
            hme[(size_t)(row + 8) * I_DIM + j] = (g1 / (1.0f + expf(-g1))) * u1;
        }
    }
}

// --------------------------------------------------------------------------
// GEMM2: Hm[M_e,4096] x W2[e]^T -> scaled by coef, atomicAdd into out.
__global__ __launch_bounds__(256, 1) void k_gemm2(const float* __restrict__ w2,
                                                  float* __restrict__ out) {
    __shared__ __nv_bfloat16 sAh[128][SMSTRIDE], sAl[128][SMSTRIDE];
    __shared__ __nv_bfloat16 sBh[128][SMSTRIDE], sBl[128][SMSTRIDE];

    const int e      = blockIdx.y;
    const int cnt    = g_cnt[e];
    const int tile_m = blockIdx.x >> 4;   // 0..63
    const int tile_n = blockIdx.x & 15;   // 0..15
    const int m0     = tile_m * 128;
    if (m0 >= cnt) return;
    const int n0     = tile_n * 128;

    const int tid  = threadIdx.x;
    const int lrow = tid >> 3;
    const int lcol = (tid & 7) << 2;

    const float* hme = g_hm + (size_t)e * CAP * I_DIM;
    const float* w2e = w2 + (size_t)e * H_DIM * I_DIM;

    const float* aPtr[4];
    const float* bPtr[4];
#pragma unroll
    for (int p = 0; p < 4; ++p) {
        aPtr[p] = hme + (size_t)(m0 + lrow + 32 * p) * I_DIM + lcol;
        bPtr[p] = w2e + (size_t)(n0 + lrow + 32 * p) * I_DIM + lcol;
    }

    const int lane = tid & 31, wid = tid >> 5;
    const int warp_m = wid >> 2, warp_n = wid & 3;
    const int gq = lane >> 2, t4 = lane & 3;

    float acc[4][4][4];
#pragma unroll
    for (int a = 0; a < 4; ++a)
#pragma unroll
        for (int b = 0; b < 4; ++b)
#pragma unroll
            for (int c = 0; c < 4; ++c) acc[a][b][c] = 0.0f;

    float4 av[4], bv[4];
#pragma unroll
    for (int p = 0; p < 4; ++p) { av[p] = *(const float4*)(aPtr[p]); bv[p] = *(const float4*)(bPtr[p]); }

    const int KT = I_DIM / 32;
#pragma unroll 1
    for (int kt = 0; kt < KT; ++kt) {
#pragma unroll
        for (int p = 0; p < 4; ++p) {
            uint2 hu, lu;
            split4(av[p], hu, lu);
            *reinterpret_cast<uint2*>(&sAh[lrow + 32 * p][lcol]) = hu;
            *reinterpret_cast<uint2*>(&sAl[lrow + 32 * p][lcol]) = lu;
            split4(bv[p], hu, lu);
            *reinterpret_cast<uint2*>(&sBh[lrow + 32 * p][lcol]) = hu;
            *reinterpret_cast<uint2*>(&sBl[lrow + 32 * p][lcol]) = lu;
        }
        __syncthreads();
        if (kt + 1 < KT) {
            int k0 = (kt + 1) * 32;
#pragma unroll
            for (int p = 0; p < 4; ++p) { av[p] = *(const float4*)(aPtr[p] + k0); bv[p] = *(const float4*)(bPtr[p] + k0); }
        }
#pragma unroll
        for (int kk = 0; kk < 32; kk += 16) {
            uint32_t bh[4][2], bl[4][2];
#pragma unroll
            for (int nf = 0; nf < 4; ++nf) {
                const __nv_bfloat16* ph = &sBh[warp_n * 32 + nf * 8 + gq][kk + t4 * 2];
                bh[nf][0] = *reinterpret_cast<const uint32_t*>(ph);
                bh[nf][1] = *reinterpret_cast<const uint32_t*>(ph + 8);
                const __nv_bfloat16* pl = &sBl[warp_n * 32 + nf * 8 + gq][kk + t4 * 2];
                bl[nf][0] = *reinterpret_cast<const uint32_t*>(pl);
                bl[nf][1] = *reinterpret_cast<const uint32_t*>(pl + 8);
            }
#pragma unroll
            for (int mf = 0; mf < 4; ++mf) {
                uint32_t ah[4], al[4];
                const __nv_bfloat16* ph = &sAh[warp_m * 64 + mf * 16 + gq][kk + t4 * 2];
                ah[0] = *reinterpret_cast<const uint32_t*>(ph);
                ah[1] = *reinterpret_cast<const uint32_t*>(ph + 8 * SMSTRIDE);
                ah[2] = *reinterpret_cast<const uint32_t*>(ph + 8);
                ah[3] = *reinterpret_cast<const uint32_t*>(ph + 8 * SMSTRIDE + 8);
                const __nv_bfloat16* pl = &sAl[warp_m * 64 + mf * 16 + gq][kk + t4 * 2];
                al[0] = *reinterpret_cast<const uint32_t*>(pl);
                al[1] = *reinterpret_cast<const uint32_t*>(pl + 8 * SMSTRIDE);
                al[2] = *reinterpret_cast<const uint32_t*>(pl + 8);
                al[3] = *reinterpret_cast<const uint32_t*>(pl + 8 * SMSTRIDE + 8);
#pragma unroll
                for (int nf = 0; nf < 4; ++nf) {
                    mma_bf16(acc[mf][nf], ah, bh[nf]);
                    mma_bf16(acc[mf][nf], ah, bl[nf]);
                    mma_bf16(acc[mf][nf], al, bh[nf]);
                }
            }
        }
        __syncthreads();
    }

    // epilogue: scale by coef, scatter-add to out (each out element gets exactly
    // TOPK commutative fp32 adds -> bitwise deterministic)
    const int* tokp = g_tok + e * LISTCAP;
    const float* cfp = g_coef + e * LISTCAP;
#pragma unroll
    for (int mf = 0; mf < 4; ++mf) {
        int mA = m0 + warp_m * 64 + mf * 16 + gq;
#pragma unroll
        for (int half = 0; half < 2; ++half) {
            int m = mA + half * 8;
            if (m < cnt) {
                int tok  = tokp[m];
                float cf = cfp[m];
                float* orow = out + (size_t)tok * H_DIM;
#pragma unroll
                for (int nf = 0; nf < 4; ++nf) {
                    int col = n0 + warp_n * 32 + nf * 8 + t4 * 2;
                    atomicAdd(&orow[col],     cf * acc[mf][nf][half * 2]);
                    atomicAdd(&orow[col + 1], cf * acc[mf][nf][half * 2 + 1]);
                }
            }
        }
    }
}

// --------------------------------------------------------------------------
extern "C" void kernel_launch(void* const* d_in, const int* in_sizes, int n_in,
                              void* d_out, int out_size) {
    const float* x   = (const float*)d_in[0];   // hidden_states [T,H]
    const int*   rt  = (const int*)d_in[1];     // expert_routing_table [T,K]
    const float* rw  = (const float*)d_in[2];   // router_weights [T,K]
    const float* w13 = (const float*)d_in[3];   // [E, 2I, H]
    const float* w2  = (const float*)d_in[4];   // [E, H, I]
    float* out = (float*)d_out;

    size_t n = (size_t)out_size;
    k_clear<<<(unsigned)((n + 255) / 256), 256>>>(out, n);
    k_route<<<(T_TOK + 255) / 256, 256>>>(rt, rw);
    k_gemm1<<<dim3(64 * 64, NE), 256>>>(x, w13);
    k_gemm2<<<dim3(64 * 16, NE), 256>>>(w2, out);
}